// round 7
// baseline (speedup 1.0000x reference)
#include <cuda_runtime.h>
#include <cstdint>

#define B_    64
#define S_    2048
#define H_    1024
#define SPLIT 16
#define CHUNK (S_ / SPLIT)      // 128 timesteps per CTA
#define TILE  8
#define NTILES (CHUNK / TILE)   // 16
#define THREADS 256             // one float4 column slice per thread
#define WARPS (THREADS / 32)

// Scratch (allocation-free: __device__ globals)
__device__ float g_expE [B_ * S_];             // exp(tanh(score)) per (b,s)
__device__ float g_partL[B_ * SPLIT];          // partial sum of exp per chunk
__device__ float g_partC[B_ * SPLIT * H_];     // partial context per chunk (4 MiB)
__device__ float g_linv [B_];                  // 1 / sum_exp per batch

// ---------------------------------------------------------------------------
// Pass 1: single DRAM read of rnn_output.
// Thread t owns H columns [4t,4t+4). Per tile of 8 timesteps:
//   1. front-batched float4 loads (MLP=8)  2. partial dots vs w4 (registers)
//   3. full warp-reduce of the 8 dots (lane 0)  4. lane0 writes 8 floats to
//      ping-pong red[p]  5. ONE __syncthreads  6. every warp redundantly
//      finishes: lanes 0-7 sum the 8 per-warp values (LDS), t=exp(tanh(.)),
//      broadcast via shuffle  7. acc += t*xr from registers.
// Ping-pong red[] makes a single barrier per tile legal. tanh in [-1,1] ->
// softmax needs no max subtraction.
// ---------------------------------------------------------------------------
__global__ __launch_bounds__(THREADS, 4)
void pass1_kernel(const float* __restrict__ x,
                  const float* __restrict__ w,
                  const float* __restrict__ bptr)
{
    __shared__ float red[2][WARPS * TILE];   // ping-pong per-warp dot partials
    __shared__ float lred[TILE];

    const int b     = blockIdx.x / SPLIT;
    const int chunk = blockIdx.x % SPLIT;
    const int tid   = threadIdx.x;
    const int warp  = tid >> 5;
    const int lane  = tid & 31;
    const float bias = __ldg(bptr);
    const float4 w4 = reinterpret_cast<const float4*>(w)[tid];

    float4 acc = make_float4(0.f, 0.f, 0.f, 0.f);
    float lsum = 0.f;                        // warp 0, lanes 0-7 accumulate

    const int s0 = chunk * CHUNK;
    const float4* xp0 = reinterpret_cast<const float4*>(x) +
                        ((size_t)b * S_ + s0) * (H_ / 4) + tid;

    #pragma unroll 1
    for (int tile = 0; tile < NTILES; tile++) {
        const float4* xp = xp0 + (size_t)tile * TILE * (H_ / 4);
        const int p = tile & 1;

        // 1. front-batched loads
        float4 xr[TILE];
        #pragma unroll
        for (int s = 0; s < TILE; s++)
            xr[s] = xp[(size_t)s * (H_ / 4)];

        // 2. partial dots
        float d[TILE];
        #pragma unroll
        for (int s = 0; s < TILE; s++)
            d[s] = xr[s].x * w4.x + xr[s].y * w4.y
                 + xr[s].z * w4.z + xr[s].w * w4.w;

        // 3. full warp reduce (lane 0 holds result)
        #pragma unroll
        for (int s = 0; s < TILE; s++) {
            #pragma unroll
            for (int off = 16; off; off >>= 1)
                d[s] += __shfl_xor_sync(0xffffffffu, d[s], off);
        }

        // 4. lane 0 publishes 8 per-warp partials
        if (lane == 0) {
            #pragma unroll
            for (int s = 0; s < TILE; s++)
                red[p][warp * TILE + s] = d[s];
        }

        // 5. single barrier per tile (ping-pong makes this sufficient)
        __syncthreads();

        // 6. redundant finish in every warp: lanes 0-7 own one timestep each
        float t = 0.f;
        if (lane < TILE) {
            float v = 0.f;
            #pragma unroll
            for (int j = 0; j < WARPS; j++)
                v += red[p][j * TILE + lane];
            t = __expf(tanhf(v + bias));
            if (warp == 0) {
                g_expE[(size_t)b * S_ + s0 + tile * TILE + lane] = t;
                lsum += t;
            }
        }

        // 7. broadcast t and accumulate from registers
        #pragma unroll
        for (int s = 0; s < TILE; s++) {
            const float ts = __shfl_sync(0xffffffffu, t, s);
            acc.x += ts * xr[s].x;
            acc.y += ts * xr[s].y;
            acc.z += ts * xr[s].z;
            acc.w += ts * xr[s].w;
        }
    }

    // write partial context (each thread owns its own float4 slot)
    reinterpret_cast<float4*>(
        g_partC + ((size_t)b * SPLIT + chunk) * H_)[tid] = acc;

    // combine warp-0 lane lsums
    if (warp == 0 && lane < TILE) lred[lane] = lsum;
    __syncthreads();
    if (tid == 0) {
        float l = 0.f;
        #pragma unroll
        for (int i = 0; i < TILE; i++) l += lred[i];
        g_partL[b * SPLIT + chunk] = l;
    }
}

// ---------------------------------------------------------------------------
// linv: one warp per batch, reduce the SPLIT partial sums.
// ---------------------------------------------------------------------------
__global__ __launch_bounds__(32)
void linv_kernel()
{
    const int b = blockIdx.x;
    const int lane = threadIdx.x;
    float l = (lane < SPLIT) ? g_partL[b * SPLIT + lane] : 0.f;
    #pragma unroll
    for (int off = 16; off; off >>= 1)
        l += __shfl_xor_sync(0xffffffffu, l, off);
    if (lane == 0) g_linv[b] = 1.f / l;
}

// ---------------------------------------------------------------------------
// Finish (flat, fully parallel): grid covers
//   items [0, B*H/4):             context[b][h4] = inv * sum_c partC[b][c][h4]
//   items [B*H/4, B*H/4 + B*S/4): weights[b][s4] = inv * expE[b][s4]
// ---------------------------------------------------------------------------
#define CTX_ITEMS (B_ * H_ / 4)     // 16384
#define WTS_ITEMS (B_ * S_ / 4)     // 32768
#define ALL_ITEMS (CTX_ITEMS + WTS_ITEMS)

__global__ __launch_bounds__(THREADS)
void finish_kernel(float* __restrict__ ctx_out, float* __restrict__ wts_out)
{
    const int i = blockIdx.x * THREADS + threadIdx.x;
    if (i < CTX_ITEMS) {
        const int b  = i / (H_ / 4);
        const int h4 = i % (H_ / 4);
        const float inv = g_linv[b];
        float4 acc = make_float4(0.f, 0.f, 0.f, 0.f);
        #pragma unroll
        for (int c = 0; c < SPLIT; c++) {          // 16 independent loads
            float4 v = reinterpret_cast<const float4*>(
                g_partC + ((size_t)b * SPLIT + c) * H_)[h4];
            acc.x += v.x; acc.y += v.y; acc.z += v.z; acc.w += v.w;
        }
        acc.x *= inv; acc.y *= inv; acc.z *= inv; acc.w *= inv;
        reinterpret_cast<float4*>(ctx_out)[i] = acc;
    } else if (i < ALL_ITEMS) {
        const int j = i - CTX_ITEMS;               // weight float4 index
        const int b = j / (S_ / 4);
        const float inv = g_linv[b];
        float4 e = reinterpret_cast<const float4*>(g_expE)[j];
        e.x *= inv; e.y *= inv; e.z *= inv; e.w *= inv;
        reinterpret_cast<float4*>(wts_out)[j] = e;
    }
}

extern "C" void kernel_launch(void* const* d_in, const int* in_sizes, int n_in,
                              void* d_out, int out_size)
{
    const float* x    = (const float*)d_in[0];   // rnn_output [B,S,H]
    const float* w    = (const float*)d_in[1];   // attn_w [H]
    const float* bptr = (const float*)d_in[2];   // attn_b scalar

    float* out = (float*)d_out;                  // context [B,H] then weights [B,S]
    float* ctx_out = out;
    float* wts_out = out + (size_t)B_ * H_;

    pass1_kernel<<<B_ * SPLIT, THREADS>>>(x, w, bptr);
    linv_kernel<<<B_, 32>>>();
    finish_kernel<<<(ALL_ITEMS + THREADS - 1) / THREADS, THREADS>>>(ctx_out, wts_out);
}